// round 2
// baseline (speedup 1.0000x reference)
#include <cuda_runtime.h>
#include <cuda_bf16.h>

#define NMASKS 128
#define W      1024
#define TILE_ROWS 128
#define TILES_PER_MASK (W / TILE_ROWS)       // 8
#define NBLOCKS (NMASKS * TILES_PER_MASK)    // 1024
#define HALO (TILE_ROWS + 2)                 // 130
#define STRIDE 35                            // gcd(35,32)=1 -> conflict-free

__device__ unsigned g_pA[NBLOCKS];
__device__ unsigned g_pC[NBLOCKS];
__device__ unsigned g_pP[NBLOCKS];
__device__ unsigned g_ctr = 0;

__device__ __forceinline__ void csa(unsigned a, unsigned b, unsigned c,
                                    unsigned &s, unsigned &cy) {
    unsigned t = a ^ b;
    s  = t ^ c;
    cy = (a & b) | (t & c);
}

__global__ __launch_bounds__(256, 8)
void prior_kernel(const float* __restrict__ masks, float* __restrict__ out) {
    // Interleaved-bitplane packed rows. Group g (128 cols) occupies slots
    // 1+4g .. 4+4g: plane k bit l = column 128g + 4l + k.
    // Guard slot 0  == "plane3 of group -1" (zero)
    // Guard slot 33 == "plane0 of group 8"  (zero)
    __shared__ unsigned srows[HALO][STRIDE];
    __shared__ unsigned red[8][3];
    __shared__ int is_last;

    const int bid  = blockIdx.x;
    const int mask = bid >> 3;           // 8 tiles per mask
    const int tile = bid & 7;
    const int r0   = tile * TILE_ROWS;
    const float4* __restrict__ base =
        (const float4*)(masks + (size_t)mask * (size_t)(W * W));

    const int tid  = threadIdx.x;
    const int lane = tid & 31;
    const int wp   = tid >> 5;           // 8 warps

    // ---- pack phase: float4 loads, 4 ballots -> 4 interleaved bitplanes ----
    for (int k = wp; k < HALO; k += 8) {
        int gr = r0 - 1 + k;
        if ((unsigned)gr >= (unsigned)W) {
            srows[k][lane] = 0u;
            if (lane < STRIDE - 32) srows[k][32 + lane] = 0u;
        } else {
            const float4* __restrict__ rowp = base + (size_t)gr * (W / 4);
            if (lane == 0) { srows[k][0] = 0u; srows[k][33] = 0u; }
            #pragma unroll
            for (int it = 0; it < 8; it++) {
                float4 v = rowp[it * 32 + lane];
                unsigned p0 = __ballot_sync(0xffffffffu, v.x > 0.0f);
                unsigned p1 = __ballot_sync(0xffffffffu, v.y > 0.0f);
                unsigned p2 = __ballot_sync(0xffffffffu, v.z > 0.0f);
                unsigned p3 = __ballot_sync(0xffffffffu, v.w > 0.0f);
                unsigned mine = (lane == 0) ? p0 : (lane == 1) ? p1
                              : (lane == 2) ? p2 : p3;
                if (lane < 4) srows[k][1 + 4 * it + lane] = mine;
            }
        }
    }
    __syncthreads();

    // ---- compute phase: 128 rows x 8 groups = 1024 group-tasks, 4/thread ----
    unsigned accA = 0, accC = 0, accP = 0;
    #pragma unroll 1
    for (int i = 0; i < 4; i++) {
        int id = tid + 256 * i;
        int g  = id & 7;                 // group 0..7
        int r  = id >> 3;                // row 0..127 -> smem rows r, r+1, r+2
        const unsigned* __restrict__ Tr = srows[r];
        const unsigned* __restrict__ Mr = srows[r + 1];
        const unsigned* __restrict__ Br = srows[r + 2];
        int s = 1 + 4 * g;

        unsigned T[4], M[4], B[4];
        #pragma unroll
        for (int k = 0; k < 4; k++) { T[k] = Tr[s + k]; M[k] = Mr[s + k]; B[k] = Br[s + k]; }
        unsigned Tp3 = Tr[s - 1], Mp3 = Mr[s - 1], Bp3 = Br[s - 1]; // plane3 of g-1
        unsigned Tn0 = Tr[s + 4], Mn0 = Mr[s + 4], Bn0 = Br[s + 4]; // plane0 of g+1

        // shifted planes for the group-boundary columns
        unsigned TSL = (T[3] << 1) | (Tp3 >> 31), TSR = (T[0] >> 1) | (Tn0 << 31);
        unsigned MSL = (M[3] << 1) | (Mp3 >> 31), MSR = (M[0] >> 1) | (Mn0 << 31);
        unsigned BSL = (B[3] << 1) | (Bp3 >> 31), BSR = (B[0] >> 1) | (Bn0 << 31);

        #pragma unroll
        for (int k = 0; k < 4; k++) {
            unsigned tl = (k > 0) ? T[k - 1] : TSL;
            unsigned ml = (k > 0) ? M[k - 1] : MSL;
            unsigned bl = (k > 0) ? B[k - 1] : BSL;
            unsigned tr = (k < 3) ? T[k + 1] : TSR;
            unsigned mr = (k < 3) ? M[k + 1] : MSR;
            unsigned br = (k < 3) ? B[k + 1] : BSR;
            unsigned tt = T[k], bot = B[k], mid = M[k];

            // CSA tree: per-bit neighbor count (0..8) as bitplanes b0..b3
            unsigned s1, c1, s2, c2, s3, c3;
            csa(tl, tt, tr, s1, c1);
            csa(ml, mr, bl, s2, c2);
            csa(bot, br, s1, s3, c3);
            unsigned s4 = s2 ^ s3, c4 = s2 & s3;
            unsigned u1, v1;
            csa(c1, c2, c3, u1, v1);
            unsigned u2 = u1 ^ c4, v2 = u1 & c4;
            unsigned b0 = s4, b1 = u2, b2 = v1 ^ v2, b3 = v1 & v2;

            accA += __popc(mid);

            unsigned conn = __popc(b0 & mid) + 2u * __popc(b1 & mid)
                          + 4u * __popc(b2 & mid) + 8u * __popc(b3 & mid);
            unsigned tot  = __popc(b0) + 2u * __popc(b1)
                          + 4u * __popc(b2) + 8u * __popc(b3);
            unsigned perim = (tot - conn)
                           + 4u * __popc(b3 & mid)
                           + 2u * __popc(b2 & b1 & mid)
                           +      __popc(b2 & b0 & mid);

            accC += conn;
            accP += perim;
        }
    }

    // ---- block reduction (exact integers) ----
    accA = __reduce_add_sync(0xffffffffu, accA);
    accC = __reduce_add_sync(0xffffffffu, accC);
    accP = __reduce_add_sync(0xffffffffu, accP);
    if (lane == 0) { red[wp][0] = accA; red[wp][1] = accC; red[wp][2] = accP; }
    __syncthreads();

    if (tid == 0) {
        unsigned a = 0, c = 0, p = 0;
        #pragma unroll
        for (int w2 = 0; w2 < 8; w2++) { a += red[w2][0]; c += red[w2][1]; p += red[w2][2]; }
        g_pA[bid] = a; g_pC[bid] = c; g_pP[bid] = p;
        __threadfence();
        unsigned ticket = atomicInc(&g_ctr, NBLOCKS - 1);  // wraps to 0 -> replayable
        is_last = (ticket == NBLOCKS - 1);
    }
    __syncthreads();

    // ---- last block: final reduction + scoring ----
    if (is_last && tid < NMASKS) {
        volatile unsigned* vA = g_pA;
        volatile unsigned* vC = g_pC;
        volatile unsigned* vP = g_pP;
        unsigned a = 0, c = 0, p = 0;
        #pragma unroll
        for (int t2 = 0; t2 < TILES_PER_MASK; t2++) {
            int j = tid * TILES_PER_MASK + t2;
            a += vA[j]; c += vC[j]; p += vP[j];
        }
        float area  = (float)a;
        float conn  = (float)c;
        float perim = (float)p;

        float safe_area  = (area > 0.0f) ? area : 1.0f;
        float area_ratio = area / (float)(W * W);
        float area_score = (area_ratio >= 0.001f && area_ratio <= 0.5f) ? 1.0f : 0.1f;

        float comp_score = (conn > 0.0f)
            ? fminf(1.0f, 10.0f / (conn / safe_area + 1e-6f))
            : 0.1f;

        float par = perim / safe_area;
        float shape_score = (area > 0.0f)
            ? ((par <= 100.0f) ? 1.0f : fmaxf(0.1f, 100.0f / (par + 1e-6f)))
            : 0.1f;

        float validity = 0.4f * area_score + 0.3f * comp_score + 0.3f * shape_score;
        out[tid] = fmaxf(0.05f, validity);
    }
}

extern "C" void kernel_launch(void* const* d_in, const int* in_sizes, int n_in,
                              void* d_out, int out_size) {
    const float* masks = (const float*)d_in[0];
    float* out = (float*)d_out;
    (void)in_sizes; (void)n_in; (void)out_size;

    prior_kernel<<<NBLOCKS, 256>>>(masks, out);
}